// round 2
// baseline (speedup 1.0000x reference)
#include <cuda_runtime.h>
#include <cstdint>

// Problem constants: B=8, S=4096, H=16, E=64, s=64
#define NB 8
#define NH 16
#define NE 64
#define NS 64
#define STOT 4096

#define TWO_PI 6.283185307179586476925f

// Per-head dense operator M[h][n][j]  (n,j in [0,64))
__device__ float g_M[NH * NS * NS];

// ---------------------------------------------------------------------------
// Setup kernel: one block per head h.
// Computes Z = rfft_127(w_h) by direct DFT, then
//   M[n][j] = (1/126) * sum_{k=0}^{63} c_k * Re( Z[k] * conj(w127^{k(63+j)}) * w126^{kn} )
// with c_0 = c_63 = 1, else 2 (the k=63 Nyquist term's imag part vanishes
// automatically since w126^{63n} = (-1)^n).  Also writes the z_pb output.
// ---------------------------------------------------------------------------
__global__ __launch_bounds__(512, 1)
void fftbias_setup(const float* __restrict__ w,
                   const float* __restrict__ o_,
                   float* __restrict__ out2) {
    const int h = blockIdx.x;
    const int tid = threadIdx.x;

    extern __shared__ float smA[];
    float2* ZW      = (float2*)smA;           // 4096 float2
    float2* F       = ZW + 4096;              // 4096 float2
    float2* root127 = F + 4096;               // 127
    float2* root126 = root127 + 127;          // 126
    float2* Zsh     = root126 + 126;          // 64
    float*  zsh     = (float*)(Zsh + 64);     // 127
    float*  osh     = zsh + 127;              // 64
    float*  zp      = osh + 64;               // 64

    if (tid < 127) {
        float sv, cv;
        sincosf(TWO_PI * (float)tid / 127.0f, &sv, &cv);
        root127[tid] = make_float2(cv, sv);
        zsh[tid] = w[h * 127 + tid];
    }
    if (tid < 126) {
        float sv, cv;
        sincosf(TWO_PI * (float)tid / 126.0f, &sv, &cv);
        root126[tid] = make_float2(cv, sv);
    }
    if (tid < 64) { osh[tid] = o_[tid]; zp[tid] = 0.0f; }
    __syncthreads();

    // Z[k] = sum_u z[u] * w127^{-k u}
    if (tid < 64) {
        const int k = tid;
        float zr = 0.f, zi = 0.f;
        int m = 0;
        for (int u = 0; u < 127; ++u) {
            float2 rt = root127[m];
            float zu = zsh[u];
            zr += zu * rt.x;
            zi -= zu * rt.y;
            m += k; if (m >= 127) m -= 127;
        }
        Zsh[k] = make_float2(zr, zi);
    }
    __syncthreads();

    // ZW[k][j] = c_k * Z[k] * conj(w127^{k(63+j)});  F[k][n] = w126^{kn}
    #pragma unroll
    for (int r = 0; r < 8; ++r) {
        int idx = tid + r * 512;
        int k = idx >> 6, j = idx & 63;
        int m = (k * (63 + j)) % 127;
        float2 rt = root127[m];
        float2 Zk = Zsh[k];
        float c = (k == 0 || k == 63) ? (1.0f / 126.0f) : (2.0f / 126.0f);
        float wr = rt.x, wi = -rt.y;
        ZW[idx] = make_float2(c * (Zk.x * wr - Zk.y * wi),
                              c * (Zk.x * wi + Zk.y * wr));
        int m2 = (k * j) % 126;     // here j plays the role of n for F
        F[idx] = root126[m2];
    }
    __syncthreads();

    // M[n][j] = sum_k Re(ZW[k][j] * F[k][n])
    #pragma unroll
    for (int r = 0; r < 8; ++r) {
        int idx = tid + r * 512;
        int n = idx >> 6, j = idx & 63;
        float acc = 0.f;
        #pragma unroll
        for (int k = 0; k < 64; ++k) {
            float2 a = ZW[k * 64 + j];
            float2 f = F[k * 64 + n];
            acc += a.x * f.x - a.y * f.y;
        }
        g_M[h * 4096 + idx] = acc;
        // zp[n] = s * sum_j M[n][j] * o_[j]
        atomicAdd(&zp[n], 64.0f * acc * osh[j]);
    }
    __syncthreads();

    // z_pb output: out2[(i*64+j)*16 + h] = zp[j] + zp[i]
    for (int idx = tid; idx < 4096; idx += 512) {
        int i = idx >> 6, j = idx & 63;
        out2[(size_t)idx * 16 + h] = zp[j] + zp[i];
    }
}

// ---------------------------------------------------------------------------
// Main kernel: one block per (b,h). 512 threads.
// Phase 1: stream v[b,:,h,:] (1 MiB) through a smem slab, producing
//          v_s[e][j] and u_s[e][i] in one DRAM pass.
// Phase 2: rv[e][n] = sum_j M[n][j] v_s[e][j]; ru likewise from u_s.
// Phase 3: out[b, i*64+j, h, e] = rv[e][j] + ru[e][i]  (float4 stores).
// ---------------------------------------------------------------------------
__global__ __launch_bounds__(512, 1)
void fftbias_main(const float* __restrict__ v, float* __restrict__ out) {
    const int b = blockIdx.x >> 4;
    const int h = blockIdx.x & 15;
    const int tid = threadIdx.x;
    const int e = tid & 63;
    const int g = tid >> 6;          // 0..7

    extern __shared__ float sm[];
    float* vs   = sm;                 // 64*65
    float* us   = vs + 64 * 65;       // 64*65
    float* rvs  = us + 64 * 65;       // 64*64  (phase-1 scratch, then rv[n][e])
    float* rus  = rvs + 64 * 64;      // 64*64  (ru[n][e])
    float* slab = rus + 64 * 64;      // 64*64  (phase-1 slab, then M cache)

    const float* vb = v + ((size_t)b * STOT * NH + h) * NE;  // [t*1024 + e]

    float vacc[8];
    #pragma unroll
    for (int k = 0; k < 8; ++k) vacc[k] = 0.f;

    for (int i = 0; i < 64; ++i) {
        // load slab rows t = i*64 + j (j = 0..63), 64 floats each
        const float4* src = (const float4*)(vb + (size_t)i * 64 * 1024);
        #pragma unroll
        for (int r = 0; r < 2; ++r) {
            int idx = tid + r * 512;          // 0..1023
            int j = idx >> 4, q = idx & 15;
            ((float4*)slab)[j * 16 + q] = src[(size_t)j * 256 + q];
        }
        __syncthreads();

        float up = 0.f;
        #pragma unroll
        for (int k = 0; k < 8; ++k) {
            float x = slab[(g + 8 * k) * 64 + e];
            vacc[k] += x;                     // v_s[e][g+8k] partial over i
            up += x;                          // u_s[e][i] partial over j-subset
        }
        rvs[g * 64 + e] = up;                 // scratch for cross-g reduce
        __syncthreads();

        if (tid < 64) {                       // tid == e
            float ssum = 0.f;
            #pragma unroll
            for (int g2 = 0; g2 < 8; ++g2) ssum += rvs[g2 * 64 + tid];
            us[tid * 65 + i] = ssum;
        }
    }

    #pragma unroll
    for (int k = 0; k < 8; ++k) vs[e * 65 + g + 8 * k] = vacc[k];
    __syncthreads();

    // cache M[h] in smem (reuse slab)
    {
        const float4* Msrc = (const float4*)(g_M + h * 4096);
        #pragma unroll
        for (int r = 0; r < 2; ++r)
            ((float4*)slab)[tid + r * 512] = Msrc[tid + r * 512];
    }
    __syncthreads();

    float rv[8], ru[8];
    #pragma unroll
    for (int k = 0; k < 8; ++k) { rv[k] = 0.f; ru[k] = 0.f; }

    for (int j = 0; j < 64; ++j) {
        float a  = vs[e * 65 + j];
        float bb = us[e * 65 + j];
        #pragma unroll
        for (int k = 0; k < 8; ++k) {
            float m = slab[(g + 8 * k) * 64 + j];   // broadcast across warp
            rv[k] += m * a;
            ru[k] += m * bb;
        }
    }

    #pragma unroll
    for (int k = 0; k < 8; ++k) {
        int n = g + 8 * k;
        rvs[n * 64 + e] = rv[k];
        rus[n * 64 + e] = ru[k];
    }
    __syncthreads();

    // Phase 3: coalesced float4 output
    const int q = tid & 15;          // float4 slot within e
    const int rg = tid >> 4;         // 0..31 row group
    float* ob = out + ((size_t)b * STOT * NH + h) * NE;
    #pragma unroll 4
    for (int r = 0; r < 128; ++r) {
        int t = r * 32 + rg;
        int i = t >> 6, j = t & 63;
        float4 a = *(const float4*)&rvs[j * 64 + q * 4];
        float4 c = *(const float4*)&rus[i * 64 + q * 4];
        float4 o4 = make_float4(a.x + c.x, a.y + c.y, a.z + c.z, a.w + c.w);
        *(float4*)&ob[(size_t)t * 1024 + q * 4] = o4;
    }
}

// ---------------------------------------------------------------------------
extern "C" void kernel_launch(void* const* d_in, const int* in_sizes, int n_in,
                              void* d_out, int out_size) {
    const float* v  = (const float*)d_in[0];   // (8,4096,16,64) f32
    const float* w  = (const float*)d_in[1];   // (1,16,127) f32
    const float* o_ = (const float*)d_in[2];   // (64,) f32
    float* out  = (float*)d_out;
    float* out2 = out + (size_t)NB * STOT * NH * NE;   // z_pb region

    const int smem_setup = 69632;   // ~69 KB
    const int smem_main  = (64 * 65 * 2 + 64 * 64 * 3) * 4;  // 82432 B

    cudaFuncSetAttribute(fftbias_setup,
                         cudaFuncAttributeMaxDynamicSharedMemorySize, smem_setup);
    cudaFuncSetAttribute(fftbias_main,
                         cudaFuncAttributeMaxDynamicSharedMemorySize, smem_main);

    fftbias_setup<<<NH, 512, smem_setup>>>(w, o_, out2);
    fftbias_main<<<NB * NH, 512, smem_main>>>(v, out);
}

// round 3
// speedup vs baseline: 1.7370x; 1.7370x over previous
#include <cuda_runtime.h>
#include <cstdint>

// Problem constants: B=8, S=4096, H=16, E=64, s=64
#define NB 8
#define NH 16
#define NE 64
#define NS 64
#define STOT 4096

#define TWO_PI 6.283185307179586476925f

__device__ __forceinline__ void cp16(float* dst, const float* src) {
    uint32_t s = (uint32_t)__cvta_generic_to_shared(dst);
    asm volatile("cp.async.cg.shared.global [%0], [%1], 16;" :: "r"(s), "l"(src));
}
__device__ __forceinline__ void cp_commit() {
    asm volatile("cp.async.commit_group;");
}

// ---------------------------------------------------------------------------
// Single fused kernel: one block per (b,h), 512 threads.
//
// Prologue : issue 3 slab prefetches, then build the dense per-head operator
//            M[n][j] (the rfft127 * conv * irfft126 chain collapses to a
//            64x64 matrix) while those loads fly. b==0 blocks also emit z_pb.
// Phase 1  : stream v[b,:,h,:] (1 MiB) through a 4-stage cp.async pipeline,
//            producing v_s[e][j] (register accum) and u_s[e][i] (smem atomics)
//            in one DRAM pass.
// Phase 2  : rv[e][n] = sum_j M[n][j] v_s[e][j];  ru likewise from u_s.
// Phase 3  : out[b, i*64+j, h, e] = rv[e][j] + ru[e][i]  (streaming float4).
// ---------------------------------------------------------------------------
__global__ __launch_bounds__(512, 1)
void fftbias_fused(const float* __restrict__ v,
                   const float* __restrict__ w,
                   const float* __restrict__ o_,
                   float* __restrict__ out,
                   float* __restrict__ out2) {
    const int b = blockIdx.x >> 4;
    const int h = blockIdx.x & 15;
    const int tid = threadIdx.x;
    const int e = tid & 63;
    const int g = tid >> 6;          // 0..7

    extern __shared__ float sm[];
    float* slab = sm;                 // 4 stages * 4096 floats = 64 KB
    float* Msh  = sm + 16384;         // 4096
    float* vs   = sm + 20480;         // 64*65
    float* us   = sm + 24640;         // 64*65
    float* rvs  = sm + 28800;         // 64*64
    float* rus  = sm + 32896;         // 64*64
    float* misc = sm + 36992;         // ~1024

    // prologue aliases (dead regions during prologue)
    float2* ZW = (float2*)rvs;        // 4096 float2 (spans rvs+rus)
    float2* F  = (float2*)vs;         // 4096 float2 (spans vs+us)
    float2* root127 = (float2*)misc;          // 127
    float2* root126 = root127 + 127;          // 126
    float2* Zsh     = root126 + 126;          // 64
    float*  zsh     = (float*)(Zsh + 64);     // 127
    float*  osh     = zsh + 127;              // 64
    float*  zp      = osh + 64;               // 64

    const float* vb = v + ((size_t)b * STOT * NH + h) * NE;  // elem [t*1024 + e]

    // ---- issue first 3 slab prefetches (stages 0..2) BEFORE any compute ----
    #pragma unroll
    for (int p = 0; p < 3; ++p) {
        #pragma unroll
        for (int r = 0; r < 2; ++r) {
            int idx = tid + r * 512;          // 0..1023 (float4 slots)
            int j = idx >> 4, q = idx & 15;
            cp16(slab + p * 4096 + j * 64 + q * 4,
                 vb + ((size_t)(p * 64 + j)) * 1024 + q * 4);
        }
        cp_commit();
    }

    // ---- prologue: build M_h while loads fly --------------------------------
    if (tid < 127) {
        float sv, cv;
        sincosf(TWO_PI * (float)tid / 127.0f, &sv, &cv);
        root127[tid] = make_float2(cv, sv);
        zsh[tid] = w[h * 127 + tid];
    }
    if (tid < 126) {
        float sv, cv;
        sincosf(TWO_PI * (float)tid / 126.0f, &sv, &cv);
        root126[tid] = make_float2(cv, sv);
    }
    if (tid < 64) osh[tid] = o_[tid];
    __syncthreads();

    // Z[k] = rfft_127(w_h)[k], k = 0..63 (direct DFT via mod-indexed roots)
    if (tid < 64) {
        const int k = tid;
        float zr = 0.f, zi = 0.f;
        int m = 0;
        for (int u = 0; u < 127; ++u) {
            float2 rt = root127[m];
            float zu = zsh[u];
            zr += zu * rt.x;
            zi -= zu * rt.y;
            m += k; if (m >= 127) m -= 127;
        }
        Zsh[k] = make_float2(zr, zi);
    }
    __syncthreads();

    // ZW[k][j] = c_k * Z[k] * conj(w127^{k(63+j)});  F[k][n] = w126^{kn}
    #pragma unroll
    for (int r = 0; r < 8; ++r) {
        int idx = tid + r * 512;
        int k = idx >> 6, j = idx & 63;
        int m = (k * (63 + j)) % 127;
        float2 rt = root127[m];
        float2 Zk = Zsh[k];
        float c = (k == 0 || k == 63) ? (1.0f / 126.0f) : (2.0f / 126.0f);
        float wr = rt.x, wi = -rt.y;
        ZW[idx] = make_float2(c * (Zk.x * wr - Zk.y * wi),
                              c * (Zk.x * wi + Zk.y * wr));
        int m2 = (k * j) % 126;               // j plays the role of n for F
        F[idx] = root126[m2];
    }
    __syncthreads();

    // M[n][j] = sum_k Re(ZW[k][j] * F[k][n])
    #pragma unroll
    for (int r = 0; r < 8; ++r) {
        int idx = tid + r * 512;
        int n = idx >> 6, j = idx & 63;
        float acc = 0.f;
        #pragma unroll
        for (int k = 0; k < 64; ++k) {
            float2 a = ZW[k * 64 + j];
            float2 f = F[k * 64 + n];
            acc += a.x * f.x - a.y * f.y;
        }
        Msh[idx] = acc;
    }
    __syncthreads();

    // b==0 blocks: compute zp and write the z_pb output (one block per head)
    if (b == 0) {
        if (tid < 64) {
            float acc = 0.f;
            #pragma unroll
            for (int j = 0; j < 64; ++j) acc += Msh[tid * 64 + j] * osh[j];
            zp[tid] = 64.0f * acc;
        }
        __syncthreads();
        for (int idx = tid; idx < 4096; idx += 512) {
            int i = idx >> 6, j = idx & 63;
            out2[(size_t)idx * 16 + h] = zp[j] + zp[i];
        }
    }

    // zero u_s accumulator (region was F during prologue)
    for (int idx = tid; idx < 64 * 65; idx += 512) us[idx] = 0.f;
    // NOTE: first in-loop __syncthreads orders this before any atomicAdd.

    // ---- Phase 1: 4-stage pipelined streaming reduce ------------------------
    float vacc[8];
    #pragma unroll
    for (int k = 0; k < 8; ++k) vacc[k] = 0.f;

    for (int i = 0; i < 64; ++i) {
        asm volatile("cp.async.wait_group 2;");
        __syncthreads();

        // prefetch slab i+3 into stage (i+3)&3 (its last reader finished at
        // iteration i-1; the sync above makes reuse safe)
        if (i + 3 < 64) {
            int ip = i + 3, st = ip & 3;
            #pragma unroll
            for (int r = 0; r < 2; ++r) {
                int idx = tid + r * 512;
                int j = idx >> 4, q = idx & 15;
                cp16(slab + st * 4096 + j * 64 + q * 4,
                     vb + ((size_t)(ip * 64 + j)) * 1024 + q * 4);
            }
        }
        cp_commit();   // empty groups near the tail keep wait_group bookkeeping exact

        const float* sl = slab + (i & 3) * 4096;
        float up = 0.f;
        #pragma unroll
        for (int k = 0; k < 8; ++k) {
            float x = sl[(g + 8 * k) * 64 + e];
            vacc[k] += x;                     // v_s[e][g+8k] partial over i
            up += x;                          // u_s[e][i] partial over j-subset
        }
        atomicAdd(&us[e * 65 + i], up);       // conflict-free banks (stride 65)
    }

    #pragma unroll
    for (int k = 0; k < 8; ++k) vs[e * 65 + g + 8 * k] = vacc[k];
    __syncthreads();

    // ---- Phase 2: dense 64x64 matvecs per e --------------------------------
    float rv[8], ru[8];
    #pragma unroll
    for (int k = 0; k < 8; ++k) { rv[k] = 0.f; ru[k] = 0.f; }

    for (int j = 0; j < 64; ++j) {
        float a  = vs[e * 65 + j];
        float bb = us[e * 65 + j];
        #pragma unroll
        for (int k = 0; k < 8; ++k) {
            float m = Msh[(g + 8 * k) * 64 + j];   // warp-broadcast
            rv[k] += m * a;
            ru[k] += m * bb;
        }
    }

    #pragma unroll
    for (int k = 0; k < 8; ++k) {
        int n = g + 8 * k;
        rvs[n * 64 + e] = rv[k];
        rus[n * 64 + e] = ru[k];
    }
    __syncthreads();

    // ---- Phase 3: streaming float4 output ----------------------------------
    const int q = tid & 15;          // float4 slot within e
    const int rg = tid >> 4;         // 0..31 row group
    float* ob = out + ((size_t)b * STOT * NH + h) * NE;
    #pragma unroll 4
    for (int r = 0; r < 128; ++r) {
        int t = r * 32 + rg;
        int i = t >> 6, j = t & 63;
        float4 a = *(const float4*)&rvs[j * 64 + q * 4];
        float4 c = *(const float4*)&rus[i * 64 + q * 4];
        float4 o4 = make_float4(a.x + c.x, a.y + c.y, a.z + c.z, a.w + c.w);
        __stcs((float4*)&ob[(size_t)t * 1024 + q * 4], o4);
    }
}

// ---------------------------------------------------------------------------
extern "C" void kernel_launch(void* const* d_in, const int* in_sizes, int n_in,
                              void* d_out, int out_size) {
    const float* v  = (const float*)d_in[0];   // (8,4096,16,64) f32
    const float* w  = (const float*)d_in[1];   // (1,16,127) f32
    const float* o_ = (const float*)d_in[2];   // (64,) f32
    float* out  = (float*)d_out;
    float* out2 = out + (size_t)NB * STOT * NH * NE;   // z_pb region

    const int smem_bytes = (36992 + 1024) * 4;   // ~148.5 KB

    cudaFuncSetAttribute(fftbias_fused,
                         cudaFuncAttributeMaxDynamicSharedMemorySize, smem_bytes);

    fftbias_fused<<<NB * NH, 512, smem_bytes>>>(v, w, o_, out, out2);
}